// round 1
// baseline (speedup 1.0000x reference)
#include <cuda_runtime.h>
#include <cstdint>
#include <cstddef>

// Scratch for H = tanh(xx @ W1), tf32-rounded fp32 values, [M=8192][160].
__device__ float g_H[8192 * 160];

__device__ __forceinline__ unsigned f2tf32(float f) {
    unsigned u;
    asm("cvt.rna.tf32.f32 %0, %1;" : "=r"(u) : "f"(f));
    return u;
}

__device__ __forceinline__ void mma_tf32(float c[4], const unsigned a[4],
                                         unsigned b0, unsigned b1) {
    asm volatile(
        "mma.sync.aligned.m16n8k8.row.col.f32.tf32.tf32.f32 "
        "{%0,%1,%2,%3}, {%4,%5,%6,%7}, {%8,%9}, {%0,%1,%2,%3};\n"
        : "+f"(c[0]), "+f"(c[1]), "+f"(c[2]), "+f"(c[3])
        : "r"(a[0]), "r"(a[1]), "r"(a[2]), "r"(a[3]), "r"(b0), "r"(b1));
}

// ---------------------------------------------------------------------------
// GEMM1: H[M,160] = tanh( (x + sx*tmx) @ W1[D,160] )
// sx computed on the fly: sx[r] = xprev[r] - x[r], xprev = x[r-1] or state row i1.
// Block: 64 rows x full 160 cols, K-loop over D in steps of 32.
// 8 warps arranged 2(m) x 4(n): warp tile = 32 rows x 40 cols.
// ---------------------------------------------------------------------------
__global__ void __launch_bounds__(256, 1)
gemm1_kernel(const float* __restrict__ x, const float* __restrict__ state,
             const float* __restrict__ tmx, const float* __restrict__ w1,
             const int* __restrict__ ip, int S, int D, int srows)
{
    __shared__ unsigned As[64][36];    // pad 36: (4*row+col)%32 conflict-free
    __shared__ unsigned Bs[32][168];   // pad 168: (8*row+col)%32 conflict-free

    const int tid  = threadIdx.x;
    const int lane = tid & 31;
    const int warp = tid >> 5;
    const int wm   = warp & 1;   // rows wm*32
    const int wn   = warp >> 1;  // cols wn*40
    const int gid  = lane >> 2;
    const int tg   = lane & 3;
    const int m0   = blockIdx.x * 64;
    const int i1   = srows * ip[0] + 1;

    float acc[2][5][4];
    #pragma unroll
    for (int a = 0; a < 2; a++)
        #pragma unroll
        for (int b = 0; b < 5; b++)
            #pragma unroll
            for (int c = 0; c < 4; c++) acc[a][b][c] = 0.f;

    // per-thread load coordinates
    int Ar[2], Ak[2];
    #pragma unroll
    for (int it = 0; it < 2; it++) { int e = tid + it * 256; Ar[it] = e >> 3; Ak[it] = (e & 7) * 4; }
    int Br[5], Bc[5];
    #pragma unroll
    for (int it = 0; it < 5; it++) { int e = tid + it * 256; Br[it] = e / 40; Bc[it] = (e % 40) * 4; }

    float4 xa[2], xpa[2], ta[2], wb[5];

    auto fetch = [&](int k0) {
        #pragma unroll
        for (int it = 0; it < 2; it++) {
            int gr = m0 + Ar[it];
            int gk = k0 + Ak[it];
            xa[it] = *reinterpret_cast<const float4*>(x + (size_t)gr * D + gk);
            ta[it] = *reinterpret_cast<const float4*>(tmx + gk);
            const float* pp;
            if ((gr % S) == 0)
                pp = state + ((size_t)(gr / S) * srows + i1) * D + gk;
            else
                pp = x + (size_t)(gr - 1) * D + gk;
            xpa[it] = *reinterpret_cast<const float4*>(pp);
        }
        #pragma unroll
        for (int it = 0; it < 5; it++)
            wb[it] = *reinterpret_cast<const float4*>(w1 + (size_t)(k0 + Br[it]) * 160 + Bc[it]);
    };

    auto store_smem = [&]() {
        #pragma unroll
        for (int it = 0; it < 2; it++) {
            const float* px = reinterpret_cast<const float*>(&xa[it]);
            const float* pp = reinterpret_cast<const float*>(&xpa[it]);
            const float* pt = reinterpret_cast<const float*>(&ta[it]);
            #pragma unroll
            for (int j = 0; j < 4; j++) {
                float v = px[j] + (pp[j] - px[j]) * pt[j];
                As[Ar[it]][Ak[it] + j] = f2tf32(v);
            }
        }
        #pragma unroll
        for (int it = 0; it < 5; it++) {
            const float* pw = reinterpret_cast<const float*>(&wb[it]);
            #pragma unroll
            for (int j = 0; j < 4; j++)
                Bs[Br[it]][Bc[it] + j] = f2tf32(pw[j]);
        }
    };

    const int nkt = D / 32;
    fetch(0);
    store_smem();
    __syncthreads();

    for (int kt = 0; kt < nkt; kt++) {
        if (kt + 1 < nkt) fetch((kt + 1) * 32);

        #pragma unroll
        for (int kk = 0; kk < 4; kk++) {
            unsigned a[2][4];
            #pragma unroll
            for (int mi = 0; mi < 2; mi++) {
                int ar = wm * 32 + mi * 16 + gid;
                int ac = kk * 8 + tg;
                a[mi][0] = As[ar][ac];
                a[mi][1] = As[ar + 8][ac];
                a[mi][2] = As[ar][ac + 4];
                a[mi][3] = As[ar + 8][ac + 4];
            }
            #pragma unroll
            for (int nt = 0; nt < 5; nt++) {
                int bc = wn * 40 + nt * 8 + gid;
                unsigned b0 = Bs[kk * 8 + tg][bc];
                unsigned b1 = Bs[kk * 8 + tg + 4][bc];
                mma_tf32(acc[0][nt], a[0], b0, b1);
                mma_tf32(acc[1][nt], a[1], b0, b1);
            }
        }
        __syncthreads();
        if (kt + 1 < nkt) {
            store_smem();
            __syncthreads();
        }
    }

    // epilogue: tanh, round to tf32, store to g_H
    #pragma unroll
    for (int mi = 0; mi < 2; mi++)
        #pragma unroll
        for (int nt = 0; nt < 5; nt++) {
            int gc = wn * 40 + nt * 8 + 2 * tg;
            #pragma unroll
            for (int h = 0; h < 2; h++) {
                int gr = m0 + wm * 32 + mi * 16 + gid + h * 8;
                float2 v;
                v.x = __uint_as_float(f2tf32(tanhf(acc[mi][nt][2 * h])));
                v.y = __uint_as_float(f2tf32(tanhf(acc[mi][nt][2 * h + 1])));
                *reinterpret_cast<float2*>(g_H + (size_t)gr * 160 + gc) = v;
            }
        }
}

// ---------------------------------------------------------------------------
// GEMM2 + epilogue: for mode f (blockIdx.z):
//   y[M,D] = H[:, f*32 : f*32+32] @ W2[f]   (K = 32, single tile)
//   out[gr, f, d] = x + (xprev - x) * (maa_f[d] + y)
// Block tile 64 x 128, 8 warps as 2(m) x 4(n): warp tile 32 x 32.
// ---------------------------------------------------------------------------
__global__ void __launch_bounds__(256)
gemm2_kernel(const float* __restrict__ x, const float* __restrict__ state,
             const float* __restrict__ w2,
             const float* __restrict__ mk, const float* __restrict__ mw,
             const float* __restrict__ mv, const float* __restrict__ mr,
             const float* __restrict__ mg,
             const int* __restrict__ ip, float* __restrict__ out,
             int S, int D, int srows)
{
    __shared__ unsigned As[64][36];
    __shared__ unsigned Bs[32][136];   // pad 136: (8*row+col)%32 conflict-free

    const int tid  = threadIdx.x;
    const int lane = tid & 31;
    const int warp = tid >> 5;
    const int wm   = warp & 1;
    const int wn   = warp >> 1;
    const int gid  = lane >> 2;
    const int tg   = lane & 3;
    const int f    = blockIdx.z;
    const int m0   = blockIdx.y * 64;
    const int n0   = blockIdx.x * 128;
    const int i1   = srows * ip[0] + 1;

    // load A: H rows m0..m0+63, cols f*32..f*32+31 (already tf32 bits)
    #pragma unroll
    for (int it = 0; it < 2; it++) {
        int e = tid + it * 256;
        int r = e >> 3, k4 = (e & 7) * 4;
        float4 v = *reinterpret_cast<const float4*>(g_H + (size_t)(m0 + r) * 160 + f * 32 + k4);
        As[r][k4 + 0] = __float_as_uint(v.x);
        As[r][k4 + 1] = __float_as_uint(v.y);
        As[r][k4 + 2] = __float_as_uint(v.z);
        As[r][k4 + 3] = __float_as_uint(v.w);
    }
    // load B: W2[f][k][n0..n0+127], convert to tf32
    #pragma unroll
    for (int it = 0; it < 4; it++) {
        int e = tid + it * 256;
        int r = e >> 5, c4 = (e & 31) * 4;
        float4 v = *reinterpret_cast<const float4*>(w2 + ((size_t)f * 32 + r) * D + n0 + c4);
        Bs[r][c4 + 0] = f2tf32(v.x);
        Bs[r][c4 + 1] = f2tf32(v.y);
        Bs[r][c4 + 2] = f2tf32(v.z);
        Bs[r][c4 + 3] = f2tf32(v.w);
    }
    __syncthreads();

    float acc[2][4][4];
    #pragma unroll
    for (int a = 0; a < 2; a++)
        #pragma unroll
        for (int b = 0; b < 4; b++)
            #pragma unroll
            for (int c = 0; c < 4; c++) acc[a][b][c] = 0.f;

    #pragma unroll
    for (int kk = 0; kk < 4; kk++) {
        unsigned a[2][4];
        #pragma unroll
        for (int mi = 0; mi < 2; mi++) {
            int ar = wm * 32 + mi * 16 + gid;
            int ac = kk * 8 + tg;
            a[mi][0] = As[ar][ac];
            a[mi][1] = As[ar + 8][ac];
            a[mi][2] = As[ar][ac + 4];
            a[mi][3] = As[ar + 8][ac + 4];
        }
        #pragma unroll
        for (int nt = 0; nt < 4; nt++) {
            int bc = wn * 32 + nt * 8 + gid;
            unsigned b0 = Bs[kk * 8 + tg][bc];
            unsigned b1 = Bs[kk * 8 + tg + 4][bc];
            mma_tf32(acc[0][nt], a[0], b0, b1);
            mma_tf32(acc[1][nt], a[1], b0, b1);
        }
    }

    const float* maa = (f == 0) ? mk : (f == 1) ? mw : (f == 2) ? mv : (f == 3) ? mr : mg;

    #pragma unroll
    for (int mi = 0; mi < 2; mi++)
        #pragma unroll
        for (int nt = 0; nt < 4; nt++) {
            int gc = n0 + wn * 32 + nt * 8 + 2 * tg;
            float2 mm = *reinterpret_cast<const float2*>(maa + gc);
            #pragma unroll
            for (int h = 0; h < 2; h++) {
                int gr = m0 + wm * 32 + mi * 16 + gid + h * 8;
                float2 xv = *reinterpret_cast<const float2*>(x + (size_t)gr * D + gc);
                const float* pp;
                if ((gr % S) == 0)
                    pp = state + ((size_t)(gr / S) * srows + i1) * D + gc;
                else
                    pp = x + (size_t)(gr - 1) * D + gc;
                float2 xp = *reinterpret_cast<const float2*>(pp);
                float y0 = acc[mi][nt][2 * h];
                float y1 = acc[mi][nt][2 * h + 1];
                float2 o;
                o.x = xv.x + (xp.x - xv.x) * (mm.x + y0);
                o.y = xv.y + (xp.y - xv.y) * (mm.y + y1);
                *reinterpret_cast<float2*>(out + ((size_t)gr * 5 + f) * D + gc) = o;
            }
        }
}

// ---------------------------------------------------------------------------
// new_state: copy state, replace row i1 with x[:, S-1, :]
// ---------------------------------------------------------------------------
__global__ void state_kernel(const float* __restrict__ x, const float* __restrict__ state,
                             const int* __restrict__ ip, float* __restrict__ outs,
                             int S, int D, int srows, int total)
{
    int idx = blockIdx.x * blockDim.x + threadIdx.x;
    if (idx >= total) return;
    int i1 = srows * ip[0] + 1;
    int d = idx % D;
    int r = (idx / D) % srows;
    int b = idx / (D * srows);
    outs[idx] = (r == i1) ? x[((size_t)b * S + (S - 1)) * D + d] : state[idx];
}

extern "C" void kernel_launch(void* const* d_in, const int* in_sizes, int n_in,
                              void* d_out, int out_size)
{
    const float* x     = (const float*)d_in[0];
    const float* state = (const float*)d_in[1];
    const float* tmx   = (const float*)d_in[2];
    const float* w1    = (const float*)d_in[3];
    const float* w2    = (const float*)d_in[4];
    const float* mk    = (const float*)d_in[5];
    const float* mw    = (const float*)d_in[6];
    const float* mv    = (const float*)d_in[7];
    const float* mr    = (const float*)d_in[8];
    const float* mg    = (const float*)d_in[9];
    const int*   ip    = (const int*)d_in[10];
    float* out = (float*)d_out;

    const int D     = in_sizes[2];                  // time_maa_x -> D
    const int srows = 2 + D / 32;                   // 2 + HEAD_SIZE
    const int Bb    = in_sizes[1] / (srows * D);
    const int M     = in_sizes[0] / D;              // B*S
    const int S     = M / Bb;

    gemm1_kernel<<<M / 64, 256>>>(x, state, tmx, w1, ip, S, D, srows);
    gemm2_kernel<<<dim3(D / 128, M / 64, 5), 256>>>(x, state, w2, mk, mw, mv, mr, mg,
                                                    ip, out, S, D, srows);

    long long main_sz = (long long)M * 5 * D;
    long long st_sz   = (long long)Bb * srows * D;
    if ((long long)out_size >= main_sz + st_sz) {
        int total = (int)st_sz;
        state_kernel<<<(total + 255) / 256, 256>>>(x, state, ip, out + main_sz,
                                                   S, D, srows, total);
    }
}

// round 3
// speedup vs baseline: 1.1327x; 1.1327x over previous
#include <cuda_runtime.h>
#include <cstdint>
#include <cstddef>

// ---------------- scratch ----------------
__device__ float g_H[8192 * 160];        // tanh(xx@W1), tf32-rounded
__device__ float g_W1[2048 * 160];       // tf32-rounded w1
__device__ float g_W2[5 * 32 * 2048];    // tf32-rounded w2

__device__ __forceinline__ unsigned f2tf32(float f) {
    unsigned u;
    asm("cvt.rna.tf32.f32 %0, %1;" : "=r"(u) : "f"(f));
    return u;
}

__device__ __forceinline__ void mma_tf32(float c[4], const unsigned a[4],
                                         unsigned b0, unsigned b1) {
    asm volatile(
        "mma.sync.aligned.m16n8k8.row.col.f32.tf32.tf32.f32 "
        "{%0,%1,%2,%3}, {%4,%5,%6,%7}, {%8,%9}, {%0,%1,%2,%3};\n"
        : "+f"(c[0]), "+f"(c[1]), "+f"(c[2]), "+f"(c[3])
        : "r"(a[0]), "r"(a[1]), "r"(a[2]), "r"(a[3]), "r"(b0), "r"(b1));
}

__device__ __forceinline__ void cp16(uint32_t dst, const void* src) {
    asm volatile("cp.async.cg.shared.global [%0], [%1], 16;\n" :: "r"(dst), "l"(src));
}
__device__ __forceinline__ void cp_commit() { asm volatile("cp.async.commit_group;\n"); }
__device__ __forceinline__ void cp_wait0()  { asm volatile("cp.async.wait_group 0;\n" ::: "memory"); }

__device__ __forceinline__ uint32_t smem_u32(const void* p) {
    return (uint32_t)__cvta_generic_to_shared(p);
}

// ---------------------------------------------------------------------------
// convert kernel: round w1, w2 to tf32 once per launch
// ---------------------------------------------------------------------------
__global__ void conv_kernel(const float* __restrict__ w1, const float* __restrict__ w2,
                            int n1, int n2)
{
    int idx = (blockIdx.x * blockDim.x + threadIdx.x) * 4;
    if (idx < n1) {
        float4 v = *reinterpret_cast<const float4*>(w1 + idx);
        float4 o;
        o.x = __uint_as_float(f2tf32(v.x)); o.y = __uint_as_float(f2tf32(v.y));
        o.z = __uint_as_float(f2tf32(v.z)); o.w = __uint_as_float(f2tf32(v.w));
        *reinterpret_cast<float4*>(g_W1 + idx) = o;
    }
    if (idx < n2) {
        float4 v = *reinterpret_cast<const float4*>(w2 + idx);
        float4 o;
        o.x = __uint_as_float(f2tf32(v.x)); o.y = __uint_as_float(f2tf32(v.y));
        o.z = __uint_as_float(f2tf32(v.z)); o.w = __uint_as_float(f2tf32(v.w));
        *reinterpret_cast<float4*>(g_W2 + idx) = o;
    }
}

// ---------------------------------------------------------------------------
// GEMM1: H[M,160] = tanh( (x + sx*tmx) @ W1[D,160] ), W1 pre-rounded tf32.
// Block: 64 rows x 160 cols. 8 warps 2(m) x 4(n): warp tile 32 x 40.
// A (token-shift mix) built in regs -> smem; B via cp.async double-buffer.
// ---------------------------------------------------------------------------
#define G1_SMEM (2*64*36*4 + 2*32*168*4)

__global__ void __launch_bounds__(256, 2)
gemm1_kernel(const float* __restrict__ x, const float* __restrict__ state,
             const float* __restrict__ tmx,
             const int* __restrict__ ip, int S, int D, int srows)
{
    extern __shared__ unsigned char dynsmem[];
    unsigned (*As)[64][36]  = reinterpret_cast<unsigned (*)[64][36]>(dynsmem);
    unsigned (*Bs)[32][168] = reinterpret_cast<unsigned (*)[32][168]>(dynsmem + 2*64*36*4);

    const int tid  = threadIdx.x;
    const int lane = tid & 31;
    const int warp = tid >> 5;
    const int wm   = warp & 1;
    const int wn   = warp >> 1;
    const int gid  = lane >> 2;
    const int tg   = lane & 3;
    const int m0   = blockIdx.x * 64;
    const int i1   = srows * ip[0] + 1;

    float acc[2][5][4];
    #pragma unroll
    for (int a = 0; a < 2; a++)
        #pragma unroll
        for (int b = 0; b < 5; b++)
            #pragma unroll
            for (int c = 0; c < 4; c++) acc[a][b][c] = 0.f;

    int Ar[2], Ak[2];
    #pragma unroll
    for (int it = 0; it < 2; it++) { int e = tid + it * 256; Ar[it] = e >> 3; Ak[it] = (e & 7) * 4; }
    int Br[5], Bc[5];
    #pragma unroll
    for (int it = 0; it < 5; it++) { int e = tid + it * 256; Br[it] = e / 40; Bc[it] = (e % 40) * 4; }

    unsigned va[2][4];   // mixed A values (tf32 bits)

    auto fetchA = [&](int k0) {
        #pragma unroll
        for (int it = 0; it < 2; it++) {
            int gr = m0 + Ar[it];
            int gk = k0 + Ak[it];
            float4 xv = *reinterpret_cast<const float4*>(x + (size_t)gr * D + gk);
            float4 tv = *reinterpret_cast<const float4*>(tmx + gk);
            const float* pp;
            if ((gr % S) == 0)
                pp = state + ((size_t)(gr / S) * srows + i1) * D + gk;
            else
                pp = x + (size_t)(gr - 1) * D + gk;
            float4 xp = *reinterpret_cast<const float4*>(pp);
            va[it][0] = f2tf32(xv.x + (xp.x - xv.x) * tv.x);
            va[it][1] = f2tf32(xv.y + (xp.y - xv.y) * tv.y);
            va[it][2] = f2tf32(xv.z + (xp.z - xv.z) * tv.z);
            va[it][3] = f2tf32(xv.w + (xp.w - xv.w) * tv.w);
        }
    };
    auto storeA = [&](int buf) {
        #pragma unroll
        for (int it = 0; it < 2; it++)
            #pragma unroll
            for (int j = 0; j < 4; j++)
                As[buf][Ar[it]][Ak[it] + j] = va[it][j];
    };
    auto cpB = [&](int k0, int buf) {
        #pragma unroll
        for (int it = 0; it < 5; it++)
            cp16(smem_u32(&Bs[buf][Br[it]][Bc[it]]),
                 g_W1 + (size_t)(k0 + Br[it]) * 160 + Bc[it]);
    };

    const int nkt = D / 32;

    cpB(0, 0); cp_commit();
    fetchA(0); storeA(0);
    cp_wait0();
    __syncthreads();

    for (int kt = 0; kt < nkt; kt++) {
        const int cur = kt & 1;
        const bool hasNext = (kt + 1 < nkt);
        if (hasNext) {
            cpB((kt + 1) * 32, cur ^ 1); cp_commit();
            fetchA((kt + 1) * 32);
        }

        #pragma unroll
        for (int kk = 0; kk < 4; kk++) {
            unsigned a[2][4];
            #pragma unroll
            for (int mi = 0; mi < 2; mi++) {
                int ar = wm * 32 + mi * 16 + gid;
                int ac = kk * 8 + tg;
                a[mi][0] = As[cur][ar][ac];
                a[mi][1] = As[cur][ar + 8][ac];
                a[mi][2] = As[cur][ar][ac + 4];
                a[mi][3] = As[cur][ar + 8][ac + 4];
            }
            #pragma unroll
            for (int nt = 0; nt < 5; nt++) {
                int bc = wn * 40 + nt * 8 + gid;
                unsigned b0 = Bs[cur][kk * 8 + tg][bc];
                unsigned b1 = Bs[cur][kk * 8 + tg + 4][bc];
                mma_tf32(acc[0][nt], a[0], b0, b1);
                mma_tf32(acc[1][nt], a[1], b0, b1);
            }
        }
        if (hasNext) {
            storeA(cur ^ 1);
            cp_wait0();
        }
        __syncthreads();
    }

    // epilogue: tanh -> tf32-rounded -> g_H
    #pragma unroll
    for (int mi = 0; mi < 2; mi++)
        #pragma unroll
        for (int nt = 0; nt < 5; nt++) {
            int gc = wn * 40 + nt * 8 + 2 * tg;
            #pragma unroll
            for (int h = 0; h < 2; h++) {
                int gr = m0 + wm * 32 + mi * 16 + gid + h * 8;
                float2 v;
                v.x = __uint_as_float(f2tf32(tanhf(acc[mi][nt][2 * h])));
                v.y = __uint_as_float(f2tf32(tanhf(acc[mi][nt][2 * h + 1])));
                *reinterpret_cast<float2*>(g_H + (size_t)gr * 160 + gc) = v;
            }
        }
}

// ---------------------------------------------------------------------------
// GEMM2 + epilogue, all 5 modes per block:
//   per mode f: y = H[:, f*32:(f+1)*32] @ W2[f]  (K=32)
//   out[gr, f, d] = x + (xprev - x) * (maa_f[d] + y)
// Block tile 64 x 128; x tile cached in smem ONCE for all 5 modes.
// xprev rows are x rows shifted by one: row r-1 of the cached tile; only the
// boundary row (r==0) needs an extra 128-col strip (Xp0).
// ---------------------------------------------------------------------------
#define G2_AS   (2*64*36*4)
#define G2_BS   (2*32*136*4)
#define G2_XV   (64*132*4)
#define G2_XP   (128*4)
#define G2_SMEM (G2_AS + G2_BS + G2_XV + G2_XP)

__global__ void __launch_bounds__(256, 2)
gemm2_kernel(const float* __restrict__ x, const float* __restrict__ state,
             const float* __restrict__ mk, const float* __restrict__ mw,
             const float* __restrict__ mv, const float* __restrict__ mr,
             const float* __restrict__ mg,
             const int* __restrict__ ip, float* __restrict__ out,
             int S, int D, int srows)
{
    extern __shared__ unsigned char dynsmem[];
    unsigned (*As)[64][36]  = reinterpret_cast<unsigned (*)[64][36]>(dynsmem);
    unsigned (*Bs)[32][136] = reinterpret_cast<unsigned (*)[32][136]>(dynsmem + G2_AS);
    float    (*Xv)[132]     = reinterpret_cast<float (*)[132]>(dynsmem + G2_AS + G2_BS);
    float*    Xp0           = reinterpret_cast<float*>(dynsmem + G2_AS + G2_BS + G2_XV);

    const int tid  = threadIdx.x;
    const int lane = tid & 31;
    const int warp = tid >> 5;
    const int wm   = warp & 1;
    const int wn   = warp >> 1;
    const int gid  = lane >> 2;
    const int tg   = lane & 3;
    const int m0   = blockIdx.y * 64;
    const int n0   = blockIdx.x * 128;
    const int i1   = srows * ip[0] + 1;

    auto cpA = [&](int f, int buf) {
        #pragma unroll
        for (int it = 0; it < 2; it++) {
            int e = tid + it * 256;
            int r = e >> 3, k4 = (e & 7) * 4;
            cp16(smem_u32(&As[buf][r][k4]),
                 g_H + (size_t)(m0 + r) * 160 + f * 32 + k4);
        }
    };
    auto cpB = [&](int f, int buf) {
        #pragma unroll
        for (int it = 0; it < 4; it++) {
            int e = tid + it * 256;
            int r = e >> 5, c4 = (e & 31) * 4;
            cp16(smem_u32(&Bs[buf][r][c4]),
                 g_W2 + ((size_t)f * 32 + r) * D + n0 + c4);
        }
    };

    // prologue: A0, B0, x tile, boundary row
    cpA(0, 0);
    cpB(0, 0);
    #pragma unroll
    for (int it = 0; it < 8; it++) {
        int e = tid + it * 256;
        int r = e >> 5, c4 = (e & 31) * 4;
        cp16(smem_u32(&Xv[r][c4]), x + (size_t)(m0 + r) * D + n0 + c4);
    }
    if (tid < 32) {
        int c4 = tid * 4;
        const float* src;
        if ((m0 % S) == 0)
            src = state + ((size_t)(m0 / S) * srows + i1) * D + n0 + c4;
        else
            src = x + (size_t)(m0 - 1) * D + n0 + c4;
        cp16(smem_u32(&Xp0[c4]), src);
    }
    cp_commit();
    cp_wait0();
    __syncthreads();

    for (int f = 0; f < 5; f++) {
        const int cur = f & 1;
        if (f < 4) {
            cpA(f + 1, cur ^ 1);
            cpB(f + 1, cur ^ 1);
            cp_commit();
        }

        float acc[2][4][4];
        #pragma unroll
        for (int a = 0; a < 2; a++)
            #pragma unroll
            for (int b = 0; b < 4; b++)
                #pragma unroll
                for (int c = 0; c < 4; c++) acc[a][b][c] = 0.f;

        #pragma unroll
        for (int kk = 0; kk < 4; kk++) {
            unsigned a[2][4];
            #pragma unroll
            for (int mi = 0; mi < 2; mi++) {
                int ar = wm * 32 + mi * 16 + gid;
                int ac = kk * 8 + tg;
                a[mi][0] = As[cur][ar][ac];
                a[mi][1] = As[cur][ar + 8][ac];
                a[mi][2] = As[cur][ar][ac + 4];
                a[mi][3] = As[cur][ar + 8][ac + 4];
            }
            #pragma unroll
            for (int nt = 0; nt < 4; nt++) {
                int bc = wn * 32 + nt * 8 + gid;
                unsigned b0 = Bs[cur][kk * 8 + tg][bc];
                unsigned b1 = Bs[cur][kk * 8 + tg + 4][bc];
                mma_tf32(acc[0][nt], a[0], b0, b1);
                mma_tf32(acc[1][nt], a[1], b0, b1);
            }
        }

        const float* maa = (f == 0) ? mk : (f == 1) ? mw : (f == 2) ? mv : (f == 3) ? mr : mg;

        #pragma unroll
        for (int mi = 0; mi < 2; mi++)
            #pragma unroll
            for (int nt = 0; nt < 4; nt++) {
                int lc = wn * 32 + nt * 8 + 2 * tg;
                int gc = n0 + lc;
                float2 mm = *reinterpret_cast<const float2*>(maa + gc);
                #pragma unroll
                for (int h = 0; h < 2; h++) {
                    int r  = wm * 32 + mi * 16 + gid + h * 8;
                    int gr = m0 + r;
                    float2 xv = *reinterpret_cast<float2*>(&Xv[r][lc]);
                    float2 xp;
                    if (r == 0) xp = *reinterpret_cast<float2*>(&Xp0[lc]);
                    else        xp = *reinterpret_cast<float2*>(&Xv[r - 1][lc]);
                    float y0 = acc[mi][nt][2 * h];
                    float y1 = acc[mi][nt][2 * h + 1];
                    float2 o;
                    o.x = xv.x + (xp.x - xv.x) * (mm.x + y0);
                    o.y = xv.y + (xp.y - xv.y) * (mm.y + y1);
                    *reinterpret_cast<float2*>(out + ((size_t)gr * 5 + f) * D + gc) = o;
                }
            }

        if (f < 4) cp_wait0();
        __syncthreads();
    }
}

// ---------------------------------------------------------------------------
// new_state: copy state, replace row i1 with x[:, S-1, :]
// ---------------------------------------------------------------------------
__global__ void state_kernel(const float* __restrict__ x, const float* __restrict__ state,
                             const int* __restrict__ ip, float* __restrict__ outs,
                             int S, int D, int srows, int total)
{
    int idx = blockIdx.x * blockDim.x + threadIdx.x;
    if (idx >= total) return;
    int i1 = srows * ip[0] + 1;
    int d = idx % D;
    int r = (idx / D) % srows;
    int b = idx / (D * srows);
    outs[idx] = (r == i1) ? x[((size_t)b * S + (S - 1)) * D + d] : state[idx];
}

extern "C" void kernel_launch(void* const* d_in, const int* in_sizes, int n_in,
                              void* d_out, int out_size)
{
    const float* x     = (const float*)d_in[0];
    const float* state = (const float*)d_in[1];
    const float* tmx   = (const float*)d_in[2];
    const float* w1    = (const float*)d_in[3];
    const float* w2    = (const float*)d_in[4];
    const float* mk    = (const float*)d_in[5];
    const float* mw    = (const float*)d_in[6];
    const float* mv    = (const float*)d_in[7];
    const float* mr    = (const float*)d_in[8];
    const float* mg    = (const float*)d_in[9];
    const int*   ip    = (const int*)d_in[10];
    float* out = (float*)d_out;

    const int D     = in_sizes[2];
    const int srows = 2 + D / 32;
    const int Bb    = in_sizes[1] / (srows * D);
    const int M     = in_sizes[0] / D;
    const int S     = M / Bb;
    const int n1    = in_sizes[3];
    const int n2    = in_sizes[4];

    static bool attr_done = false;
    if (!attr_done) {
        cudaFuncSetAttribute(gemm1_kernel, cudaFuncAttributeMaxDynamicSharedMemorySize, G1_SMEM);
        cudaFuncSetAttribute(gemm2_kernel, cudaFuncAttributeMaxDynamicSharedMemorySize, G2_SMEM);
        attr_done = true;
    }

    int nmax = n1 > n2 ? n1 : n2;
    conv_kernel<<<(nmax / 4 + 255) / 256, 256>>>(w1, w2, n1, n2);
    gemm1_kernel<<<M / 64, 256, G1_SMEM>>>(x, state, tmx, ip, S, D, srows);
    gemm2_kernel<<<dim3(D / 128, M / 64), 256, G2_SMEM>>>(x, state, mk, mw, mv, mr, mg,
                                                          ip, out, S, D, srows);

    long long main_sz = (long long)M * 5 * D;
    long long st_sz   = (long long)Bb * srows * D;
    if ((long long)out_size >= main_sz + st_sz) {
        int total = (int)st_sz;
        state_kernel<<<(total + 255) / 256, 256>>>(x, state, ip, out + main_sz,
                                                   S, D, srows, total);
    }
}